// round 1
// baseline (speedup 1.0000x reference)
#include <cuda_runtime.h>
#include <cuda_bf16.h>
#include <math.h>
#include <stdint.h>

// ---------------- problem constants ----------------
#define BATCH   2
#define CIN     128
#define COUT    512
#define DD      8
#define HH      32
#define WW      32
#define POS     (DD*HH*WW)          // 8192
#define NCOL    (BATCH*POS)         // 16384
#define KDIM    (CIN*27)            // 3456
#define NANCH   9
#define NPROP   (POS*NANCH)         // 73728 per batch
#define PRE_NMS 2048
#define POST_NMS 300
#define NMS_TH  0.7f
#define HROWS   72                  // 18 cls + 54 bbox

// ---------------- static scratch (no allocs allowed) ----------------
__device__ float g_col[(size_t)KDIM * NCOL];          // im2col  [K][N]
__device__ float g_x  [(size_t)COUT * NCOL];          // conv out [512][N]
__device__ float g_h  [(size_t)HROWS * NCOL];         // head out [72][N]
__device__ float g_wh [HROWS * 512];                  // packed head weights
__device__ float g_bh [HROWS];                        // packed head bias
__device__ float g_scores[BATCH * NPROP];
__device__ float g_boxes [(size_t)BATCH * NPROP * 6];
__device__ unsigned long long g_cand[BATCH][4096];
__device__ float g_sboxes[(size_t)BATCH * PRE_NMS * 6];
__device__ unsigned long long g_mask[(size_t)BATCH * PRE_NMS * 32];

// ---------------- im2col ----------------
__global__ void im2col_kernel(const float* __restrict__ bf) {
    int idx = blockIdx.x * 256 + threadIdx.x;
    const int total = KDIM * NCOL;
    if (idx >= total) return;
    int n = idx & (NCOL - 1);
    int k = idx >> 14;               // NCOL = 16384 = 2^14
    int c = k / 27; int rem = k % 27;
    int kd = rem / 9, kh = (rem % 9) / 3, kw = rem % 3;
    int b = n >> 13;                 // POS = 8192 = 2^13
    int pos = n & (POS - 1);
    int d = pos >> 10, h = (pos >> 5) & 31, w = pos & 31;
    int zd = d + kd - 1, zh = h + kh - 1, zw = w + kw - 1;
    float v = 0.f;
    if ((unsigned)zd < DD && (unsigned)zh < HH && (unsigned)zw < WW)
        v = bf[((( (size_t)b * CIN + c) * DD + zd) * HH + zh) * WW + zw];
    g_col[idx] = v;
}

// ---------------- SGEMM 128x128x8, 8x8 per thread, double-buffered ----------------
__device__ __forceinline__ void mma_tile(const float (*As)[128], const float (*Bs)[128],
                                         float acc[8][8], int ty, int tx) {
#pragma unroll
    for (int kk = 0; kk < 8; kk++) {
        float a[8], bv[8];
        *(float4*)&a[0]  = *(const float4*)&As[kk][ty * 4];
        *(float4*)&a[4]  = *(const float4*)&As[kk][64 + ty * 4];
        *(float4*)&bv[0] = *(const float4*)&Bs[kk][tx * 4];
        *(float4*)&bv[4] = *(const float4*)&Bs[kk][64 + tx * 4];
#pragma unroll
        for (int i = 0; i < 8; i++)
#pragma unroll
            for (int j = 0; j < 8; j++)
                acc[i][j] = fmaf(a[i], bv[j], acc[i][j]);
    }
}

__global__ __launch_bounds__(256, 2)
void sgemm128(const float* __restrict__ A, const float* __restrict__ B,
              float* __restrict__ C, const float* __restrict__ bias,
              int M, int N, int K, int doRelu) {
    __shared__ float As[2][8][128];
    __shared__ float Bs[2][8][128];
    const int tid = threadIdx.x;
    const int m0 = blockIdx.y * 128;
    const int n0 = blockIdx.x * 128;
    const int tx = tid & 15;
    const int ty = tid >> 4;
    const int aRow = tid >> 1;
    const int aCol = (tid & 1) * 4;
    const int bRow = tid >> 5;
    const int bCol = (tid & 31) * 4;

    float acc[8][8];
#pragma unroll
    for (int i = 0; i < 8; i++)
#pragma unroll
        for (int j = 0; j < 8; j++) acc[i][j] = 0.f;

    float4 av, bv;
    {
        int gm = m0 + aRow;
        if (gm < M) av = *(const float4*)(A + (size_t)gm * K + aCol);
        else        av = make_float4(0.f, 0.f, 0.f, 0.f);
        bv = *(const float4*)(B + (size_t)bRow * N + n0 + bCol);
        As[0][aCol + 0][aRow] = av.x; As[0][aCol + 1][aRow] = av.y;
        As[0][aCol + 2][aRow] = av.z; As[0][aCol + 3][aRow] = av.w;
        *(float4*)&Bs[0][bRow][bCol] = bv;
    }
    __syncthreads();

    int cur = 0;
    for (int kt = 8; kt < K; kt += 8) {
        int gm = m0 + aRow;
        if (gm < M) av = *(const float4*)(A + (size_t)gm * K + kt + aCol);
        else        av = make_float4(0.f, 0.f, 0.f, 0.f);
        bv = *(const float4*)(B + (size_t)(kt + bRow) * N + n0 + bCol);

        mma_tile(As[cur], Bs[cur], acc, ty, tx);

        int nxt = cur ^ 1;
        As[nxt][aCol + 0][aRow] = av.x; As[nxt][aCol + 1][aRow] = av.y;
        As[nxt][aCol + 2][aRow] = av.z; As[nxt][aCol + 3][aRow] = av.w;
        *(float4*)&Bs[nxt][bRow][bCol] = bv;
        __syncthreads();
        cur = nxt;
    }
    mma_tile(As[cur], Bs[cur], acc, ty, tx);

#pragma unroll
    for (int ii = 0; ii < 2; ii++) {
#pragma unroll
        for (int i = 0; i < 4; i++) {
            int gm = m0 + ii * 64 + ty * 4 + i;
            if (gm >= M) continue;
            float bb = bias[gm];
#pragma unroll
            for (int jj = 0; jj < 2; jj++) {
                float4 v;
                v.x = acc[ii * 4 + i][jj * 4 + 0] + bb;
                v.y = acc[ii * 4 + i][jj * 4 + 1] + bb;
                v.z = acc[ii * 4 + i][jj * 4 + 2] + bb;
                v.w = acc[ii * 4 + i][jj * 4 + 3] + bb;
                if (doRelu) {
                    v.x = fmaxf(v.x, 0.f); v.y = fmaxf(v.y, 0.f);
                    v.z = fmaxf(v.z, 0.f); v.w = fmaxf(v.w, 0.f);
                }
                *(float4*)(C + (size_t)gm * N + n0 + jj * 64 + tx * 4) = v;
            }
        }
    }
}

// ---------------- pack head weights ----------------
__global__ void pack_head(const float* __restrict__ Wc, const float* __restrict__ bc,
                          const float* __restrict__ Wb, const float* __restrict__ bb) {
    int idx = blockIdx.x * 256 + threadIdx.x;
    if (idx < HROWS * 512) {
        int row = idx / 512, col = idx % 512;
        g_wh[idx] = (row < 18) ? Wc[row * 512 + col] : Wb[(row - 18) * 512 + col];
    }
    if (idx < HROWS) g_bh[idx] = (idx < 18) ? bc[idx] : bb[idx - 18];
}

// ---------------- proposal: softmax, anchors, apply deltas, clip ----------------
__global__ void proposal_kernel(const float* __restrict__ im_info) {
    int idx = blockIdx.x * 256 + threadIdx.x;
    if (idx >= BATCH * NPROP) return;
    int b = idx / NPROP;
    int i = idx - b * NPROP;
    int pos = i / NANCH;
    int a = i - pos * NANCH;
    int n = b * POS + pos;

    float l0 = g_h[(size_t)a * NCOL + n];
    float l1 = g_h[(size_t)(NANCH + a) * NCOL + n];
    float mx = fmaxf(l0, l1);
    float e0 = expf(l0 - mx), e1 = expf(l1 - mx);
    g_scores[(size_t)b * NPROP + i] = e1 / (e0 + e1);

    const float* hd = g_h + (size_t)(18 + a * 6) * NCOL + n;
    float dx = hd[0 * (size_t)NCOL], dy = hd[1 * (size_t)NCOL], dz = hd[2 * (size_t)NCOL];
    float dw = hd[3 * (size_t)NCOL], dh = hd[4 * (size_t)NCOL], dd = hd[5 * (size_t)NCOL];

    int wp = pos & 31, hp = (pos >> 5) & 31, dp = pos >> 10;
    float s = 4.f * (float)(1 << (a % 3));      // 4, 8, 16
    float r = 0.5f * (float)(1 << (a / 3));     // 0.5, 1, 2
    float wsz = 8.f * s;
    float dsz = 8.f * s * r;
    const float ctr = 3.5f;
    float sx = wp * 8.f, sy = hp * 8.f, sz = dp * 8.f;

    float x1 = sx + ctr - 0.5f * (wsz - 1.f), x2 = sx + ctr + 0.5f * (wsz - 1.f);
    float y1 = sy + ctr - 0.5f * (wsz - 1.f), y2 = sy + ctr + 0.5f * (wsz - 1.f);
    float z1 = sz + ctr - 0.5f * (dsz - 1.f), z2 = sz + ctr + 0.5f * (dsz - 1.f);

    float aw = x2 - x1 + 1.f, ah = y2 - y1 + 1.f, ad = z2 - z1 + 1.f;
    float cx = x1 + 0.5f * aw, cy = y1 + 0.5f * ah, cz = z1 + 0.5f * ad;

    float pcx = dx * aw + cx, pcy = dy * ah + cy, pcz = dz * ad + cz;
    float pw = expf(dw) * aw, ph = expf(dh) * ah, pd = expf(dd) * ad;

    float ox1 = pcx - 0.5f * pw, oy1 = pcy - 0.5f * ph, oz1 = pcz - 0.5f * pd;
    float ox2 = pcx + 0.5f * pw, oy2 = pcy + 0.5f * ph, oz2 = pcz + 0.5f * pd;

    float hix = im_info[b * 3 + 2] - 1.f;
    float hiy = im_info[b * 3 + 1] - 1.f;
    float hiz = im_info[b * 3 + 0] - 1.f;
    ox1 = fminf(fmaxf(ox1, 0.f), hix); ox2 = fminf(fmaxf(ox2, 0.f), hix);
    oy1 = fminf(fmaxf(oy1, 0.f), hiy); oy2 = fminf(fmaxf(oy2, 0.f), hiy);
    oz1 = fminf(fmaxf(oz1, 0.f), hiz); oz2 = fminf(fmaxf(oz2, 0.f), hiz);

    float* ob = g_boxes + ((size_t)b * NPROP + i) * 6;
    ob[0] = ox1; ob[1] = oy1; ob[2] = oz1; ob[3] = ox2; ob[4] = oy2; ob[5] = oz2;
}

// ---------------- top-2048 select (exact jax top_k order) ----------------
__device__ __forceinline__ unsigned int rkey(float f) {
    unsigned u = __float_as_uint(f);
    u = (u & 0x80000000u) ? ~u : (u | 0x80000000u);  // orderable asc
    return ~u;                                        // asc rkey == desc score
}

__global__ __launch_bounds__(1024)
void select_topk_kernel() {
    const int b = blockIdx.x;
    const int tid = threadIdx.x;
    const float* sc = g_scores + (size_t)b * NPROP;

    __shared__ unsigned sh_hist[256];
    __shared__ unsigned sh_prefix;
    __shared__ int sh_need;
    __shared__ int sh_cnt;
    __shared__ unsigned long long s[4096];

    if (tid == 0) { sh_prefix = 0; sh_need = PRE_NMS; }
    __syncthreads();

    for (int p = 3; p >= 0; p--) {
        for (int v = tid; v < 256; v += 1024) sh_hist[v] = 0;
        __syncthreads();
        unsigned pref = sh_prefix;
        unsigned pm = (p == 3) ? 0u : (0xFFFFFFFFu << ((p + 1) * 8));
        for (int i = tid; i < NPROP; i += 1024) {
            unsigned rk = rkey(sc[i]);
            if ((rk & pm) == pref) atomicAdd(&sh_hist[(rk >> (p * 8)) & 255], 1u);
        }
        __syncthreads();
        if (tid == 0) {
            int need = sh_need;
            unsigned acc = 0;
            for (int v = 0; v < 256; v++) {
                unsigned c = sh_hist[v];
                if (need <= (int)(acc + c)) {
                    sh_prefix = pref | ((unsigned)v << (p * 8));
                    sh_need = need - (int)acc;
                    break;
                }
                acc += c;
            }
        }
        __syncthreads();
    }
    unsigned cutoff = sh_prefix;
    if (tid == 0) sh_cnt = 0;
    __syncthreads();

    for (int i = tid; i < NPROP; i += 1024) {
        unsigned rk = rkey(sc[i]);
        if (rk <= cutoff) {
            int posn = atomicAdd(&sh_cnt, 1);
            if (posn < 4096)
                g_cand[b][posn] = ((unsigned long long)rk << 32) | (unsigned)i;
        }
    }
    __syncthreads();
    int total = sh_cnt; if (total > 4096) total = 4096;
    for (int i = tid; i < 4096; i += 1024)
        s[i] = (i < total) ? g_cand[b][i] : 0xFFFFFFFFFFFFFFFFull;
    __syncthreads();

    // bitonic sort ascending (rk asc, idx asc) == (score desc, idx asc)
    for (int k = 2; k <= 4096; k <<= 1) {
        for (int j = k >> 1; j > 0; j >>= 1) {
            for (int i = tid; i < 4096; i += 1024) {
                int l = i ^ j;
                if (l > i) {
                    unsigned long long a = s[i], c = s[l];
                    bool swap = ((i & k) == 0) ? (a > c) : (a < c);
                    if (swap) { s[i] = c; s[l] = a; }
                }
            }
            __syncthreads();
        }
    }

    for (int r2 = tid; r2 < PRE_NMS; r2 += 1024) {
        unsigned idx = (unsigned)(s[r2] & 0xFFFFFFFFull);
        const float* src = g_boxes + ((size_t)b * NPROP + idx) * 6;
        float* dst = g_sboxes + ((size_t)b * PRE_NMS + r2) * 6;
#pragma unroll
        for (int c = 0; c < 6; c++) dst[c] = src[c];
    }
}

// ---------------- NMS bitmask ----------------
__global__ void nms_mask_kernel() {
    int b = blockIdx.z, jb = blockIdx.x, ib = blockIdx.y, t = threadIdx.x;
    __shared__ float cb[64][6];
    const float* sb = g_sboxes + (size_t)b * PRE_NMS * 6;
    {
        const float* p = sb + (size_t)(jb * 64 + t) * 6;
#pragma unroll
        for (int c = 0; c < 6; c++) cb[t][c] = p[c];
    }
    __syncthreads();

    int i = ib * 64 + t;
    const float* p = sb + (size_t)i * 6;
    float x1 = p[0], y1 = p[1], z1 = p[2], x2 = p[3], y2 = p[4], z2 = p[5];
    float vi = (x2 - x1 + 1.f) * (y2 - y1 + 1.f) * (z2 - z1 + 1.f);
    unsigned long long bits = 0ull;
#pragma unroll 4
    for (int jj = 0; jj < 64; jj++) {
        float ix = fmaxf(fminf(x2, cb[jj][3]) - fmaxf(x1, cb[jj][0]) + 1.f, 0.f);
        float iy = fmaxf(fminf(y2, cb[jj][4]) - fmaxf(y1, cb[jj][1]) + 1.f, 0.f);
        float iz = fmaxf(fminf(z2, cb[jj][5]) - fmaxf(z1, cb[jj][2]) + 1.f, 0.f);
        float inter = ix * iy * iz;
        float vj = (cb[jj][3] - cb[jj][0] + 1.f) * (cb[jj][4] - cb[jj][1] + 1.f)
                 * (cb[jj][5] - cb[jj][2] + 1.f);
        float iou = inter / (vi + vj - inter);
        if (iou > NMS_TH) bits |= (1ull << jj);
    }
    g_mask[((size_t)b * PRE_NMS + i) * 32 + jb] = bits;
}

// ---------------- sequential keep-scan + output ----------------
__global__ void nms_scan_kernel(float* __restrict__ out) {
    int b = blockIdx.x;
    int lane = threadIdx.x;  // 32 threads
    __shared__ unsigned short keep[POST_NMS];
    unsigned long long rem = 0ull;
    int nk = 0;
    const unsigned long long* mb = g_mask + (size_t)b * PRE_NMS * 32;
    for (int i = 0; i < PRE_NMS; i++) {
        unsigned long long w = __shfl_sync(0xffffffffu, rem, i >> 6);
        if (!((w >> (i & 63)) & 1ull)) {
            if (lane == 0 && nk < POST_NMS) keep[nk] = (unsigned short)i;
            nk++;
            rem |= mb[(size_t)i * 32 + lane];
        }
    }
    __syncwarp();
    for (int r = lane; r < POST_NMS; r += 32) {
        float* o = out + ((size_t)b * POST_NMS + r) * 7;
        o[0] = (float)b;
        if (r < nk) {
            int i = keep[r];
            const float* bx = g_sboxes + ((size_t)b * PRE_NMS + i) * 6;
#pragma unroll
            for (int c = 0; c < 6; c++) o[1 + c] = bx[c];
        } else {
#pragma unroll
            for (int c = 0; c < 6; c++) o[1 + c] = 0.f;
        }
    }
}

// ---------------- launch ----------------
extern "C" void kernel_launch(void* const* d_in, const int* in_sizes, int n_in,
                              void* d_out, int out_size) {
    const float* base_feat = (const float*)d_in[0];
    const float* im_info   = (const float*)d_in[1];
    const float* W_conv    = (const float*)d_in[4];
    const float* b_conv    = (const float*)d_in[5];
    const float* W_cls     = (const float*)d_in[6];
    const float* b_cls     = (const float*)d_in[7];
    const float* W_bbox    = (const float*)d_in[8];
    const float* b_bbox    = (const float*)d_in[9];
    float* out = (float*)d_out;

    float *p_col, *p_x, *p_h, *p_wh, *p_bh;
    cudaGetSymbolAddress((void**)&p_col, g_col);
    cudaGetSymbolAddress((void**)&p_x,   g_x);
    cudaGetSymbolAddress((void**)&p_h,   g_h);
    cudaGetSymbolAddress((void**)&p_wh,  g_wh);
    cudaGetSymbolAddress((void**)&p_bh,  g_bh);

    {   // im2col
        int total = KDIM * NCOL;
        im2col_kernel<<<(total + 255) / 256, 256>>>(base_feat);
    }
    {   // conv GEMM: [512 x 16384] = W_conv[512 x 3456] * col[3456 x 16384], +bias, relu
        dim3 grid(NCOL / 128, COUT / 128);
        sgemm128<<<grid, 256>>>(W_conv, p_col, p_x, b_conv, COUT, NCOL, KDIM, 1);
    }
    {   // pack head weights
        pack_head<<<(HROWS * 512 + 255) / 256, 256>>>(W_cls, b_cls, W_bbox, b_bbox);
    }
    {   // heads GEMM: [72 x 16384] = wh[72 x 512] * x[512 x 16384], +bias
        dim3 grid(NCOL / 128, 1);
        sgemm128<<<grid, 256>>>(p_wh, p_x, p_h, p_bh, HROWS, NCOL, 512, 0);
    }
    {   // proposals
        int total = BATCH * NPROP;
        proposal_kernel<<<(total + 255) / 256, 256>>>(im_info);
    }
    select_topk_kernel<<<BATCH, 1024>>>();
    {
        dim3 grid(PRE_NMS / 64, PRE_NMS / 64, BATCH);
        nms_mask_kernel<<<grid, 64>>>();
    }
    nms_scan_kernel<<<BATCH, 32>>>(out);
}